// round 4
// baseline (speedup 1.0000x reference)
#include <cuda_runtime.h>
#include <math.h>

#define N_TOTAL 16384
#define TPB     1024
#define EPT     (N_TOTAL / TPB)      // 16 elements per thread
#define NB      4096                 // value buckets
#define BPT     (NB / TPB)           // 4 buckets per thread

// dynamic smem layout (doubles first for alignment):
//   double bpre[NB]        32 KB   inclusive prefix of per-bucket neg sums
//   float  spos[N_TOTAL]   64 KB   compacted positive scores
//   float  sneg[N_TOTAL]   64 KB   bucket-sorted negative scores
//   int    bstart[NB+1]            exclusive bucket start offsets
//   int    bfill[NB]               histogram, then scatter cursors
#define SMEM_BYTES (NB*8 + N_TOTAL*4*2 + (NB+1)*4 + NB*4)

__device__ __forceinline__ int bidx(float x, float lo, float scale) {
    float f = (x - lo) * scale;
    f = fminf(fmaxf(f, 0.0f), (float)(NB - 1));   // NaN (0*inf) -> 0: safe
    return (int)f;
}

__global__ __launch_bounds__(TPB, 1)
void auc_kernel(const int* __restrict__ yt, const float* __restrict__ yp,
                float* __restrict__ out) {
    extern __shared__ char smraw[];
    double* bpre   = (double*)smraw;                 // [NB]
    float*  spos   = (float*)(bpre + NB);            // [N_TOTAL]
    float*  sneg   = spos + N_TOTAL;                 // [N_TOTAL]
    int*    bstart = (int*)(sneg + N_TOTAL);         // [NB+1]
    int*    bfill  = bstart + NB + 1;                // [NB]

    __shared__ float  s_f[32];
    __shared__ float  s_g[32];
    __shared__ int    s_wi[32];
    __shared__ double s_wd[32];
    __shared__ int    s_posctr;
    __shared__ float  s_lov, s_scale;

    const int tid  = threadIdx.x;
    const int lane = tid & 31;
    const int warp = tid >> 5;

    // ---- phase 0: load 16 contiguous elems/thread; local neg min/max ----
    const int base = tid * EPT;
    float vals[EPT];
    int   lab[EPT];
    {
        #pragma unroll
        for (int k = 0; k < EPT / 4; k++) {
            int4   t4 = ((const int4*)yt)[(base >> 2) + k];
            float4 v4 = ((const float4*)yp)[(base >> 2) + k];
            lab[4*k+0] = t4.x; lab[4*k+1] = t4.y; lab[4*k+2] = t4.z; lab[4*k+3] = t4.w;
            vals[4*k+0] = v4.x; vals[4*k+1] = v4.y; vals[4*k+2] = v4.z; vals[4*k+3] = v4.w;
        }
    }
    float lo =  __int_as_float(0x7f800000);   // +inf
    float hi = -__int_as_float(0x7f800000);   // -inf
    int cp = 0;
    #pragma unroll
    for (int k = 0; k < EPT; k++) {
        if (lab[k] == 1) { cp++; }
        else { lo = fminf(lo, vals[k]); hi = fmaxf(hi, vals[k]); }
    }
    if (tid == 0) s_posctr = 0;

    // ---- block min/max of negs ----
    #pragma unroll
    for (int o = 16; o > 0; o >>= 1) {
        lo = fminf(lo, __shfl_down_sync(0xffffffffu, lo, o));
        hi = fmaxf(hi, __shfl_down_sync(0xffffffffu, hi, o));
    }
    if (lane == 0) { s_f[warp] = lo; s_g[warp] = hi; }
    __syncthreads();
    if (warp == 0) {
        float l = s_f[lane], h = s_g[lane];
        #pragma unroll
        for (int o = 16; o > 0; o >>= 1) {
            l = fminf(l, __shfl_down_sync(0xffffffffu, l, o));
            h = fmaxf(h, __shfl_down_sync(0xffffffffu, h, o));
        }
        if (lane == 0) {
            float w = h - l;
            s_lov   = l;
            s_scale = (w > 0.0f) ? (float)NB / w : 0.0f;
        }
    }
    // zero histogram while warp0 finishes
    #pragma unroll
    for (int k = 0; k < BPT; k++) bfill[tid * BPT + k] = 0;
    __syncthreads();

    const float lov   = s_lov;
    const float scale = s_scale;

    // ---- phase 1: histogram negs ----
    #pragma unroll
    for (int k = 0; k < EPT; k++)
        if (lab[k] != 1) atomicAdd(&bfill[bidx(vals[k], lov, scale)], 1);
    __syncthreads();

    // ---- phase 2: exclusive scan of bucket counts -> bstart, cursors ----
    {
        int c[BPT], p[BPT];
        int run = 0;
        #pragma unroll
        for (int k = 0; k < BPT; k++) { c[k] = bfill[tid * BPT + k]; run += c[k]; p[k] = run; }
        int inc = run;
        #pragma unroll
        for (int o = 1; o < 32; o <<= 1) {
            int t = __shfl_up_sync(0xffffffffu, inc, o);
            if (lane >= o) inc += t;
        }
        if (lane == 31) s_wi[warp] = inc;
        __syncthreads();
        if (warp == 0) {
            int w = s_wi[lane];
            #pragma unroll
            for (int o = 1; o < 32; o <<= 1) {
                int t = __shfl_up_sync(0xffffffffu, w, o);
                if (lane >= o) w += t;
            }
            s_wi[lane] = w;
        }
        __syncthreads();
        int ex = inc - run + (warp > 0 ? s_wi[warp - 1] : 0);
        #pragma unroll
        for (int k = 0; k < BPT; k++) {
            int st = ex + (k > 0 ? p[k - 1] : 0);
            bstart[tid * BPT + k] = st;
            bfill [tid * BPT + k] = st;
        }
        if (tid == TPB - 1) bstart[NB] = ex + p[BPT - 1];   // = nneg
    }
    __syncthreads();

    // ---- phase 3: scatter (negs bucket-sorted, pos appended) ----
    {
        int pbase = (cp > 0) ? atomicAdd(&s_posctr, cp) : 0;
        #pragma unroll
        for (int k = 0; k < EPT; k++) {
            if (lab[k] == 1) {
                spos[pbase++] = vals[k];
            } else {
                int pos = atomicAdd(&bfill[bidx(vals[k], lov, scale)], 1);
                sneg[pos] = vals[k];
            }
        }
    }
    __syncthreads();

    // ---- phase 4: per-bucket sums -> inclusive double prefix in bpre ----
    {
        double d[BPT];
        double run = 0.0;
        #pragma unroll
        for (int k = 0; k < BPT; k++) {
            const int b = tid * BPT + k;
            const int e0 = bstart[b], e1 = bstart[b + 1];
            double s = 0.0;
            for (int j = e0; j < e1; j++) s += (double)sneg[j];
            run += s;
            d[k] = run;                         // thread-local inclusive
        }
        double inc = run;
        #pragma unroll
        for (int o = 1; o < 32; o <<= 1) {
            double t = __shfl_up_sync(0xffffffffu, inc, o);
            if (lane >= o) inc += t;
        }
        if (lane == 31) s_wd[warp] = inc;
        __syncthreads();
        if (warp == 0) {
            double w = s_wd[lane];
            #pragma unroll
            for (int o = 1; o < 32; o <<= 1) {
                double t = __shfl_up_sync(0xffffffffu, w, o);
                if (lane >= o) w += t;
            }
            s_wd[lane] = w;
        }
        __syncthreads();
        double ex = inc - run + (warp > 0 ? s_wd[warp - 1] : 0.0);
        #pragma unroll
        for (int k = 0; k < BPT; k++) bpre[tid * BPT + k] = ex + d[k];
    }
    __syncthreads();

    // ---- phase 5: O(1) query per positive row ----
    const int    npos   = s_posctr;
    const int    nneg   = bstart[NB];
    const double totsum = bpre[NB - 1];

    double acc = 0.0;
    for (int r = tid; r < npos; r += TPB) {
        const float c = 1.0f - spos[r];
        const int   b = bidx(-c, lov, scale);
        const int  e0 = bstart[b], e1 = bstart[b + 1];
        // buckets strictly above b: every term c+e > 0 exactly
        acc += (double)c * (double)(nneg - e1) + (totsum - bpre[b]);
        // boundary bucket: exact per-element hinge
        for (int j = e0; j < e1; j++) {
            const float z = c + sneg[j];
            if (z > 0.0f) acc += (double)z;
        }
    }

    // ---- final reduction ----
    #pragma unroll
    for (int o = 16; o > 0; o >>= 1)
        acc += __shfl_down_sync(0xffffffffu, acc, o);
    if (lane == 0) s_wd[warp] = acc;
    __syncthreads();
    if (warp == 0) {
        double a = s_wd[lane];
        #pragma unroll
        for (int o = 16; o > 0; o >>= 1)
            a += __shfl_down_sync(0xffffffffu, a, o);
        if (lane == 0)
            out[0] = (float)(a / ((double)npos * (double)nneg));
    }
}

extern "C" void kernel_launch(void* const* d_in, const int* in_sizes, int n_in,
                              void* d_out, int out_size) {
    const int*   yt = (const int*)d_in[0];
    const float* yp = (const float*)d_in[1];

    cudaFuncSetAttribute(auc_kernel,
                         cudaFuncAttributeMaxDynamicSharedMemorySize, SMEM_BYTES);

    auc_kernel<<<1, TPB, SMEM_BYTES>>>(yt, yp, (float*)d_out);
}

// round 5
// speedup vs baseline: 3.3898x; 3.3898x over previous
#include <cuda_runtime.h>
#include <math.h>

#define N_TOTAL 16384
#define TPB     1024
#define GRID    148
#define ROWS    8
#define EPT     (N_TOTAL / TPB)     // 16
#define PADV    64.0f               // pad magnitude: c_pad = -64, n_pad = -64

typedef unsigned long long u64;

__device__ float        g_partial[GRID];
__device__ unsigned int g_arrive = 0;

__device__ __forceinline__ u64 fadd2(u64 a, u64 b) {
    u64 r; asm("add.rn.f32x2 %0, %1, %2;" : "=l"(r) : "l"(a), "l"(b)); return r;
}
__device__ __forceinline__ u64 pk2(float x) {
    u64 r; asm("mov.b64 %0, {%1, %1};" : "=l"(r) : "f"(x)); return r;
}
__device__ __forceinline__ void upk2(float& lo, float& hi, u64 v) {
    asm("mov.b64 {%0, %1}, %2;" : "=f"(lo), "=f"(hi) : "l"(v));
}

// ---------------------------------------------------------------------------
// Persistent fused kernel.
//   phase 1: per-block deterministic compaction of pos/neg into smem (+pads)
//   phase 2: S = sum over padded RxJ grid of |c_r + n_j|
//            inner op per 2 pairs: FADD2 ; AND64 ; FADD2   (no movs)
//            padded terms have x<0 so x+|x| = 0 exactly -> contribute nothing
//   phase 3: last block: exact linear part in double, num = (lin + S)/2
// ---------------------------------------------------------------------------
__global__ __launch_bounds__(TPB, 1)
void fused_kernel(const int* __restrict__ yt, const float* __restrict__ yp,
                  float* __restrict__ out) {
    extern __shared__ float sm[];         // sneg[nneg_pad] then spos[npos_pad]
    __shared__ int    wsum[32];
    __shared__ float  s_red[32];
    __shared__ double s_dp[32];
    __shared__ double s_dn[32];
    __shared__ int    s_amlast;

    const int tid  = threadIdx.x;
    const int lane = tid & 31;
    const int warp = tid >> 5;

    // ---- phase 1a: load 16 contiguous elems/thread, count pos ----
    const int base = tid * EPT;
    int4   tt[EPT / 4];
    float4 vv[EPT / 4];
    int cp = 0;
    #pragma unroll
    for (int k = 0; k < EPT / 4; k++) {
        tt[k] = ((const int4*)yt)[(base >> 2) + k];
        vv[k] = ((const float4*)yp)[(base >> 2) + k];
        cp += (tt[k].x == 1) + (tt[k].y == 1) + (tt[k].z == 1) + (tt[k].w == 1);
    }

    // ---- phase 1b: block exclusive scan ----
    int inc = cp;
    #pragma unroll
    for (int o = 1; o < 32; o <<= 1) {
        int t = __shfl_up_sync(0xffffffffu, inc, o);
        if (lane >= o) inc += t;
    }
    if (lane == 31) wsum[warp] = inc;
    __syncthreads();
    if (warp == 0) {
        int w = wsum[lane];
        #pragma unroll
        for (int o = 1; o < 32; o <<= 1) {
            int t = __shfl_up_sync(0xffffffffu, w, o);
            if (lane >= o) w += t;
        }
        wsum[lane] = w;
    }
    __syncthreads();

    const int excl     = inc - cp + (warp > 0 ? wsum[warp - 1] : 0);
    const int npos     = wsum[31];
    const int nneg     = N_TOTAL - npos;
    const int nneg_pad = (nneg + 7) & ~7;                  // JV=8 multiple
    const int npos_pad = (npos + ROWS - 1) & ~(ROWS - 1);  // ROWS multiple
    float* sneg = sm;
    float* spos = sm + nneg_pad;

    // ---- phase 1c: scatter + pads ----
    {
        int po = excl;
        int no = base - excl;
        #pragma unroll
        for (int k = 0; k < EPT / 4; k++) {
            if (tt[k].x == 1) spos[po++] = vv[k].x; else sneg[no++] = vv[k].x;
            if (tt[k].y == 1) spos[po++] = vv[k].y; else sneg[no++] = vv[k].y;
            if (tt[k].z == 1) spos[po++] = vv[k].z; else sneg[no++] = vv[k].z;
            if (tt[k].w == 1) spos[po++] = vv[k].w; else sneg[no++] = vv[k].w;
        }
        for (int j = nneg + tid; j < nneg_pad; j += TPB) sneg[j] = -PADV;
        for (int i = npos + tid; i < npos_pad; i += TPB) spos[i] = 1.0f + PADV;
    }
    __syncthreads();

    // ---- phase 2: packed |x| sum over this block's contiguous group range --
    const int ngroups = npos_pad / ROWS;
    const int g_beg   = (int)(((long long)ngroups * blockIdx.x) / GRID);
    const int g_end   = (int)(((long long)ngroups * (blockIdx.x + 1)) / GRID);
    const u64 ABSM    = 0x7fffffff7fffffffULL;

    u64 accv2 = 0ull;
    for (int g = g_beg; g < g_end; g++) {
        const int r0 = g * ROWS;
        u64 c2[ROWS], acc2[ROWS];
        #pragma unroll
        for (int r = 0; r < ROWS; r++) {
            c2[r]   = pk2(1.0f - spos[r0 + r]);
            acc2[r] = 0ull;
        }
        for (int j = tid * 8; j < nneg_pad; j += TPB * 8) {
            const ulonglong2 A = *reinterpret_cast<const ulonglong2*>(sneg + j);
            const ulonglong2 B = *reinterpret_cast<const ulonglong2*>(sneg + j + 4);
            #pragma unroll
            for (int r = 0; r < ROWS; r++) {
                const u64 t0 = fadd2(c2[r], A.x) & ABSM;
                const u64 t1 = fadd2(c2[r], A.y) & ABSM;
                const u64 t2 = fadd2(c2[r], B.x) & ABSM;
                const u64 t3 = fadd2(c2[r], B.y) & ABSM;
                acc2[r] = fadd2(acc2[r], t0);
                acc2[r] = fadd2(acc2[r], t1);
                acc2[r] = fadd2(acc2[r], t2);
                acc2[r] = fadd2(acc2[r], t3);
            }
        }
        #pragma unroll
        for (int r = 0; r < ROWS; r++) accv2 = fadd2(accv2, acc2[r]);
    }
    float alo, ahi;
    upk2(alo, ahi, accv2);
    float accv = alo + ahi;

    // ---- block reduction (fixed order) ----
    #pragma unroll
    for (int o = 16; o > 0; o >>= 1)
        accv += __shfl_down_sync(0xffffffffu, accv, o);
    if (lane == 0) s_red[warp] = accv;
    __syncthreads();
    if (warp == 0) {
        float w = s_red[lane];
        #pragma unroll
        for (int o = 16; o > 0; o >>= 1)
            w += __shfl_down_sync(0xffffffffu, w, o);
        if (lane == 0) g_partial[blockIdx.x] = w;
    }

    // ---- phase 3: last block finalizes ----
    if (tid == 0) {
        __threadfence();
        unsigned int prev = atomicAdd(&g_arrive, 1u);
        s_amlast = (prev == GRID - 1);
    }
    __syncthreads();
    if (!s_amlast) return;
    __threadfence();

    // exact double sums of real pos/neg from this block's own smem copy
    double dp = 0.0, dn = 0.0;
    for (int i = tid; i < npos; i += TPB) dp += (double)spos[i];
    for (int i = tid; i < nneg; i += TPB) dn += (double)sneg[i];
    #pragma unroll
    for (int o = 16; o > 0; o >>= 1) {
        dp += __shfl_down_sync(0xffffffffu, dp, o);
        dn += __shfl_down_sync(0xffffffffu, dn, o);
    }
    if (lane == 0) { s_dp[warp] = dp; s_dn[warp] = dn; }
    __syncthreads();
    if (warp == 0) {
        double p = s_dp[lane], n = s_dn[lane];
        double S = 0.0;
        for (int i = lane; i < GRID; i += 32) S += (double)g_partial[i];
        #pragma unroll
        for (int o = 16; o > 0; o >>= 1) {
            p += __shfl_down_sync(0xffffffffu, p, o);
            n += __shfl_down_sync(0xffffffffu, n, o);
            S += __shfl_down_sync(0xffffffffu, S, o);
        }
        if (lane == 0) {
            // linear part over the PADDED grid (pads contribute 0 to num):
            //   Sc' = sum of c over padded rows, Sn' = sum of n over padded negs
            const double Pr  = (double)(npos_pad - npos);
            const double Pn  = (double)(nneg_pad - nneg);
            const double Sc  = (double)npos - p - (double)PADV * Pr;
            const double Snp = n - (double)PADV * Pn;
            const double lin = (double)nneg_pad * Sc + (double)npos_pad * Snp;
            const double num = 0.5 * (lin + (double)S);
            out[0] = (float)(num / ((double)npos * (double)nneg));
            g_arrive = 0u;   // reset for next graph replay
        }
    }
}

extern "C" void kernel_launch(void* const* d_in, const int* in_sizes, int n_in,
                              void* d_out, int out_size) {
    const int*   yt = (const int*)d_in[0];
    const float* yp = (const float*)d_in[1];

    const int smem_bytes = (N_TOTAL + ROWS + 8) * sizeof(float);   // ~65.6 KB
    cudaFuncSetAttribute(fused_kernel,
                         cudaFuncAttributeMaxDynamicSharedMemorySize, smem_bytes);

    fused_kernel<<<GRID, TPB, smem_bytes>>>(yt, yp, (float*)d_out);
}